// round 2
// baseline (speedup 1.0000x reference)
#include <cuda_runtime.h>

// Problem constants
#define LSEQ   256
#define NSEQ   128
#define DMODEL 256
#define HEADS  8
#define DHEAD  32
#define PDIM   128

// Scratch (device globals: allocation-free, graph-capture safe)
__device__ float g_qkv[NSEQ * LSEQ * 3 * DMODEL];   // [32768][768]  (3*D cols: q|k|v, head-major)
__device__ float g_bias[HEADS * LSEQ * LSEQ];       // [h][k][q]  (transposed for coalesced attn reads)
__device__ float g_att[NSEQ * LSEQ * DMODEL];       // [32768][256]

// ---------------------------------------------------------------------------
// Tiled SGEMM: C[M,N] = A[M,K] @ B[K,N] (+ bias[N]).  128x128 block tile,
// 8x8 per-thread microtile, 256 threads, K-step 8. M,N,K multiples of 128/8.
// ---------------------------------------------------------------------------
template <bool HAS_BIAS>
__global__ void __launch_bounds__(256) sgemm_kernel(
    const float* __restrict__ A, const float* __restrict__ B,
    const float* __restrict__ bias, float* __restrict__ C,
    int M, int N, int K)
{
    __shared__ float As[8][128];
    __shared__ float Bs[8][128];

    const int tid = threadIdx.x;
    const int bm = blockIdx.y << 7;
    const int bn = blockIdx.x << 7;

    // A tile loader: 4 floats per thread (row = tid/2, k-col = (tid&1)*4)
    const int ar = tid >> 1;
    const int ac = (tid & 1) << 2;
    // B tile loader: 4 floats per thread (k-row = tid/32, col = (tid&31)*4)
    const int kr = tid >> 5;
    const int nc = (tid & 31) << 2;

    const float* Aptr = A + (size_t)(bm + ar) * K + ac;
    const float* Bptr = B + (size_t)kr * N + bn + nc;

    const int tyr = (tid >> 4) << 3;   // microtile row offset
    const int txc = (tid & 15) << 3;   // microtile col offset

    float acc[8][8];
#pragma unroll
    for (int i = 0; i < 8; i++)
#pragma unroll
        for (int j = 0; j < 8; j++) acc[i][j] = 0.f;

    for (int k0 = 0; k0 < K; k0 += 8) {
        float4 a = *(const float4*)(Aptr + k0);
        float4 b = *(const float4*)(Bptr + (size_t)k0 * N);
        As[ac + 0][ar] = a.x;
        As[ac + 1][ar] = a.y;
        As[ac + 2][ar] = a.z;
        As[ac + 3][ar] = a.w;
        *(float4*)&Bs[kr][nc] = b;
        __syncthreads();

#pragma unroll
        for (int kk = 0; kk < 8; kk++) {
            float af[8], bf[8];
            *(float4*)&af[0] = *(const float4*)&As[kk][tyr];
            *(float4*)&af[4] = *(const float4*)&As[kk][tyr + 4];
            *(float4*)&bf[0] = *(const float4*)&Bs[kk][txc];
            *(float4*)&bf[4] = *(const float4*)&Bs[kk][txc + 4];
#pragma unroll
            for (int i = 0; i < 8; i++)
#pragma unroll
                for (int j = 0; j < 8; j++)
                    acc[i][j] = fmaf(af[i], bf[j], acc[i][j]);
        }
        __syncthreads();
    }

#pragma unroll
    for (int i = 0; i < 8; i++) {
        float* crow = C + (size_t)(bm + tyr + i) * N + bn + txc;
        if (HAS_BIAS) {
#pragma unroll
            for (int j = 0; j < 8; j++) acc[i][j] += bias[bn + txc + j];
        }
        *(float4*)(crow)     = *(float4*)&acc[i][0];
        *(float4*)(crow + 4) = *(float4*)&acc[i][4];
    }
}

// ---------------------------------------------------------------------------
// pair_bias: bias[h][k][q] = sum_p pair[q][k][p] * w_pb[p][h] + b_pb[h]
// One warp per (q,k). 65536 warps.
// ---------------------------------------------------------------------------
__global__ void __launch_bounds__(256) pair_bias_kernel(
    const float* __restrict__ pair, const float* __restrict__ w_pb,
    const float* __restrict__ b_pb, float* __restrict__ bias_out)
{
    __shared__ float w[PDIM * HEADS];
    __shared__ float bb[HEADS];
    const int tid = threadIdx.x;
    for (int i = tid; i < PDIM * HEADS; i += 256) w[i] = w_pb[i];
    if (tid < HEADS) bb[tid] = b_pb[tid];
    __syncthreads();

    const int warp = (blockIdx.x << 3) + (tid >> 5);  // 0..65535
    const int lane = tid & 31;
    const int q = warp >> 8;
    const int k = warp & 255;

    float4 p = *(const float4*)(pair + ((size_t)(q << 8) + k) * PDIM + (lane << 2));
    const int p0 = lane << 2;

    float res[HEADS];
#pragma unroll
    for (int h = 0; h < HEADS; h++) {
        float s = p.x * w[(p0 + 0) * HEADS + h]
                + p.y * w[(p0 + 1) * HEADS + h]
                + p.z * w[(p0 + 2) * HEADS + h]
                + p.w * w[(p0 + 3) * HEADS + h];
#pragma unroll
        for (int off = 16; off; off >>= 1)
            s += __shfl_xor_sync(0xFFFFFFFFu, s, off);
        res[h] = s + bb[h];
    }
    if (lane == 0) {
#pragma unroll
        for (int h = 0; h < HEADS; h++)
            bias_out[((size_t)(h << 8) + k) * LSEQ + q] = res[h];
    }
}

// ---------------------------------------------------------------------------
// Attention: one block per (n,h). Q/K/V staged to smem (padded rows), each
// thread owns one query row; online softmax; output -> g_att [n][l][h*32+d].
// Mask is int32 (bool input materialized as int32 by the harness).
// ---------------------------------------------------------------------------
__global__ void __launch_bounds__(256) attn_kernel(
    const int* __restrict__ mask, float* __restrict__ attout)
{
    extern __shared__ float sm[];
    float* Qs = sm;             // 256*33
    float* Ks = sm + 8448;      // 256*33
    float* Vs = sm + 16896;     // 256*33
    __shared__ int smask[LSEQ];

    const int n = blockIdx.x >> 3;
    const int h = blockIdx.x & 7;
    const int tid = threadIdx.x;

    const float* qkvbase = g_qkv + (size_t)(n * LSEQ) * 768 + h * DHEAD;
    for (int idx = tid; idx < LSEQ * DHEAD; idx += 256) {
        const int l = idx >> 5, d = idx & 31;
        const float* row = qkvbase + (size_t)l * 768 + d;
        Qs[l * 33 + d] = row[0];
        Ks[l * 33 + d] = row[256];
        Vs[l * 33 + d] = row[512];
    }
    smask[tid] = mask[n * LSEQ + tid];
    __syncthreads();

    const int q = tid;
    float qr[DHEAD];
#pragma unroll
    for (int d = 0; d < DHEAD; d++) qr[d] = Qs[q * 33 + d];

    const float scale = 0.17677669529663687f;  // 1/sqrt(32)
    float m = -1e30f, lsum = 0.f;
    float o[DHEAD];
#pragma unroll
    for (int d = 0; d < DHEAD; d++) o[d] = 0.f;

    const float* brow = g_bias + (size_t)h * LSEQ * LSEQ + q;  // [h][k][q]

    for (int k = 0; k < LSEQ; k++) {
        if (smask[k] == 0) continue;
        float s = 0.f;
#pragma unroll
        for (int d = 0; d < DHEAD; d++) s = fmaf(qr[d], Ks[k * 33 + d], s);
        s = fmaf(s, scale, brow[(size_t)k * LSEQ]);
        if (s <= m) {
            const float p = __expf(s - m);
            lsum += p;
#pragma unroll
            for (int d = 0; d < DHEAD; d++) o[d] = fmaf(p, Vs[k * 33 + d], o[d]);
        } else {
            const float r = __expf(m - s);
            lsum = fmaf(lsum, r, 1.0f);
#pragma unroll
            for (int d = 0; d < DHEAD; d++) o[d] = fmaf(o[d], r, Vs[k * 33 + d]);
            m = s;
        }
    }

    const float inv = (lsum > 0.f) ? (1.0f / lsum) : 0.f;
    __syncthreads();
#pragma unroll
    for (int d = 0; d < DHEAD; d++) Qs[q * 33 + d] = o[d] * inv;
    __syncthreads();

    float* obase = attout + (size_t)(n * LSEQ) * DMODEL + h * DHEAD;
    for (int idx = tid; idx < LSEQ * DHEAD; idx += 256) {
        const int l = idx >> 5, d = idx & 31;
        obase[(size_t)l * DMODEL + d] = Qs[l * 33 + d];
    }
}

// ---------------------------------------------------------------------------
// Launch
// ---------------------------------------------------------------------------
extern "C" void kernel_launch(void* const* d_in, const int* in_sizes, int n_in,
                              void* d_out, int out_size)
{
    const float* msa   = (const float*)d_in[0];
    const float* pair  = (const float*)d_in[1];
    const int*   mask  = (const int*)d_in[2];
    const float* w_qkv = (const float*)d_in[3];
    const float* w_pb  = (const float*)d_in[4];
    const float* b_pb  = (const float*)d_in[5];
    const float* w_out = (const float*)d_in[6];
    const float* b_out = (const float*)d_in[7];
    float* out = (float*)d_out;

    float *qkv_ptr, *bias_ptr, *att_ptr;
    cudaGetSymbolAddress((void**)&qkv_ptr,  g_qkv);
    cudaGetSymbolAddress((void**)&bias_ptr, g_bias);
    cudaGetSymbolAddress((void**)&att_ptr,  g_att);

    // 1) QKV = msa @ w_qkv       [32768,256]x[256,768]
    sgemm_kernel<false><<<dim3(6, 256), 256>>>(msa, w_qkv, nullptr, qkv_ptr,
                                               NSEQ * LSEQ, 3 * DMODEL, DMODEL);

    // 2) pair_bias -> [h][k][q]
    pair_bias_kernel<<<8192, 256>>>(pair, w_pb, b_pb, bias_ptr);

    // 3) attention per (n,h)
    const int attn_smem = 3 * LSEQ * 33 * (int)sizeof(float);  // 101376
    cudaFuncSetAttribute(attn_kernel, cudaFuncAttributeMaxDynamicSharedMemorySize,
                         attn_smem);
    attn_kernel<<<NSEQ * HEADS, 256, attn_smem>>>(mask, att_ptr);

    // 4) out = att @ w_out + b_out   [32768,256]x[256,256]
    sgemm_kernel<true><<<dim3(2, 256), 256>>>(att_ptr, w_out, b_out, out,
                                              NSEQ * LSEQ, DMODEL, DMODEL);
}

// round 4
// speedup vs baseline: 2.0545x; 2.0545x over previous
#include <cuda_runtime.h>
#include <cuda_fp16.h>
#include <cstdint>

#define LSEQ   256
#define NSEQ   128
#define DMODEL 256
#define HEADS  8
#define DHEAD  32
#define PDIM   128
#define MROWS  (NSEQ * LSEQ)   // 32768

// ---------------------------------------------------------------------------
// Scratch (device globals; allocation-free, graph-capture safe)
// ---------------------------------------------------------------------------
__device__ __align__(16) __half g_msa_h[MROWS * DMODEL];        // fp16 msa [32768][256]
__device__ __align__(16) __half g_wqkv_t[3 * DMODEL * DMODEL];  // [768][256]  (N-major, K contiguous)
__device__ __align__(16) __half g_wout_t[DMODEL * DMODEL];      // [256][256]
__device__ __align__(16) __half g_qkv_h[MROWS * 3 * DMODEL];    // [32768][768]
__device__ __align__(16) __half g_att_h[MROWS * DMODEL];        // [32768][256]
__device__ float g_bias[HEADS * LSEQ * LSEQ];                   // [h][k][q]

// ---------------------------------------------------------------------------
// helpers
// ---------------------------------------------------------------------------
__device__ __forceinline__ uint32_t smem_u32(const void* p) {
    uint32_t a;
    asm("{ .reg .u64 t; cvta.to.shared.u64 t, %1; cvt.u32.u64 %0, t; }" : "=r"(a) : "l"(p));
    return a;
}

#define LDMX4(r0, r1, r2, r3, addr)                                           \
    asm volatile("ldmatrix.sync.aligned.m8n8.x4.shared.b16 {%0,%1,%2,%3}, [%4];" \
                 : "=r"(r0), "=r"(r1), "=r"(r2), "=r"(r3) : "r"(addr))

__device__ __forceinline__ void mma16816(float* c, const uint32_t* a, const uint32_t* b) {
    asm volatile("mma.sync.aligned.m16n8k16.row.col.f32.f16.f16.f32 "
                 "{%0,%1,%2,%3}, {%4,%5,%6,%7}, {%8,%9}, {%0,%1,%2,%3};"
                 : "+f"(c[0]), "+f"(c[1]), "+f"(c[2]), "+f"(c[3])
                 : "r"(a[0]), "r"(a[1]), "r"(a[2]), "r"(a[3]), "r"(b[0]), "r"(b[1]));
}

// packed f32x2
__device__ __forceinline__ unsigned long long pk2(float x, float y) {
    unsigned long long r;
    asm("mov.b64 %0, {%1, %2};" : "=l"(r) : "f"(x), "f"(y));
    return r;
}
__device__ __forceinline__ float2 upk2(unsigned long long v) {
    float2 r;
    asm("mov.b64 {%0, %1}, %2;" : "=f"(r.x), "=f"(r.y) : "l"(v));
    return r;
}
__device__ __forceinline__ unsigned long long fma2(unsigned long long a, unsigned long long b,
                                                   unsigned long long c) {
    unsigned long long d;
    asm("fma.rn.f32x2 %0, %1, %2, %3;" : "=l"(d) : "l"(a), "l"(b), "l"(c));
    return d;
}

// ---------------------------------------------------------------------------
// HMMA GEMM: C[M,N] = A[M,256] @ Bt[N,256]^T.  Block tile 128x128, K=256
// fully smem-resident, 8 warps each 32(M)x64(N), mma.sync m16n8k16.
// Smem rows are 512B; 16B chunks XOR-swizzled by (row&7) -> ldmatrix
// conflict-free. FINAL=false: fp16 out (ldc cols). FINAL=true: fp32+bias.
// ---------------------------------------------------------------------------
template <bool FINAL>
__global__ void __launch_bounds__(256) gemm_hmma(
    const __half* __restrict__ A, const __half* __restrict__ Bt,
    __half* __restrict__ Ch, float* __restrict__ Cf,
    const float* __restrict__ bias, int ldc)
{
    extern __shared__ __align__(16) __half sm[];
    __half* As = sm;              // [128][256]
    __half* Bs = sm + 128 * 256;  // [128][256]

    const int tid = threadIdx.x;
    const int wid = tid >> 5, lane = tid & 31;
    const int m0 = blockIdx.y << 7;
    const int n0 = blockIdx.x << 7;

    // cooperative load: 4096 16B-chunks each for A and B
    for (int idx = tid; idx < 8192; idx += 256) {
        const int isB = idx >> 12;
        const int r = (idx >> 5) & 127;
        const int c = idx & 31;
        const __half* src = isB ? Bt + (size_t)(n0 + r) * 256 + c * 8
                                : A  + (size_t)(m0 + r) * 256 + c * 8;
        __half* dst = (isB ? Bs : As) + r * 256 + ((c ^ (r & 7)) * 8);
        *(uint4*)dst = *(const uint4*)src;
    }
    __syncthreads();

    const int wm = (wid >> 1) * 32;   // warp m offset (0,32,64,96)
    const int wn = (wid & 1) * 64;    // warp n offset (0,64)

    // per-lane ldmatrix address components
    const int a_row = (lane & 7) + ((lane >> 3) & 1) * 8;  // 0..15
    const int a_cadd = lane >> 4;                          // 0..1
    const int b_row = (lane & 7) + ((lane >> 4) & 1) * 8;
    const int b_cadd = (lane >> 3) & 1;

    const uint32_t AsA = smem_u32(As), BsA = smem_u32(Bs);
    uint32_t a_base[2], a_sw[2];
#pragma unroll
    for (int i = 0; i < 2; i++) {
        const int r = wm + 16 * i + a_row;
        a_base[i] = AsA + r * 512;
        a_sw[i] = r & 7;
    }
    uint32_t b_base[4], b_sw[4];
#pragma unroll
    for (int j = 0; j < 4; j++) {
        const int r = wn + 16 * j + b_row;
        b_base[j] = BsA + r * 512;
        b_sw[j] = r & 7;
    }

    float acc[2][8][4];
#pragma unroll
    for (int i = 0; i < 2; i++)
#pragma unroll
        for (int j = 0; j < 8; j++)
#pragma unroll
            for (int t = 0; t < 4; t++) acc[i][j][t] = 0.f;

#pragma unroll
    for (int kk = 0; kk < 16; kk++) {
        const int k8 = kk * 2;  // 16B-chunk index of this k-step
        uint32_t a[2][4];
#pragma unroll
        for (int i = 0; i < 2; i++) {
            const uint32_t addr = a_base[i] + (((k8 + a_cadd) ^ a_sw[i]) << 4);
            LDMX4(a[i][0], a[i][1], a[i][2], a[i][3], addr);
        }
        uint32_t b[8][2];
#pragma unroll
        for (int j = 0; j < 4; j++) {
            const uint32_t addr = b_base[j] + (((k8 + b_cadd) ^ b_sw[j]) << 4);
            LDMX4(b[2 * j][0], b[2 * j][1], b[2 * j + 1][0], b[2 * j + 1][1], addr);
        }
#pragma unroll
        for (int i = 0; i < 2; i++)
#pragma unroll
            for (int j = 0; j < 8; j++)
                mma16816(acc[i][j], a[i], b[j]);
    }

    // epilogue
    const int tr = lane >> 2;
    const int tc = (lane & 3) * 2;
#pragma unroll
    for (int i = 0; i < 2; i++) {
        const int row = m0 + wm + 16 * i + tr;
#pragma unroll
        for (int j = 0; j < 8; j++) {
            const int col = n0 + wn + 8 * j + tc;
            if (FINAL) {
                const float b0 = __ldg(&bias[col]), b1 = __ldg(&bias[col + 1]);
                float2 v0 = make_float2(acc[i][j][0] + b0, acc[i][j][1] + b1);
                float2 v1 = make_float2(acc[i][j][2] + b0, acc[i][j][3] + b1);
                *(float2*)(Cf + (size_t)row * ldc + col) = v0;
                *(float2*)(Cf + (size_t)(row + 8) * ldc + col) = v1;
            } else {
                __half2 h0 = __floats2half2_rn(acc[i][j][0], acc[i][j][1]);
                __half2 h1 = __floats2half2_rn(acc[i][j][2], acc[i][j][3]);
                *(__half2*)(Ch + (size_t)row * ldc + col) = h0;
                *(__half2*)(Ch + (size_t)(row + 8) * ldc + col) = h1;
            }
        }
    }
}

// ---------------------------------------------------------------------------
// fp32 -> fp16 bulk convert
// ---------------------------------------------------------------------------
__global__ void __launch_bounds__(512) cvt_msa_kernel(const float4* __restrict__ in,
                                                      __half2* __restrict__ out, int n4)
{
    for (int i = blockIdx.x * 512 + threadIdx.x; i < n4; i += gridDim.x * 512) {
        float4 v = in[i];
        out[2 * i]     = __floats2half2_rn(v.x, v.y);
        out[2 * i + 1] = __floats2half2_rn(v.z, v.w);
    }
}

// transpose + convert: out[n*K + k] = in[k*N + n]
__global__ void __launch_bounds__(256) cvt_wT_kernel(const float* __restrict__ in,
                                                     __half* __restrict__ out, int K, int N)
{
    int idx = blockIdx.x * 256 + threadIdx.x;
    if (idx < N * K) {
        int n = idx / K, k = idx - n * K;
        out[idx] = __float2half(in[k * N + n]);
    }
}

// ---------------------------------------------------------------------------
// pair_bias: bias[h][k][q] = sum_p pair[q][k][p] * w_pb[p][h] + b_pb[h]
// ---------------------------------------------------------------------------
__global__ void __launch_bounds__(256) pair_bias_kernel(
    const float* __restrict__ pair, const float* __restrict__ w_pb,
    const float* __restrict__ b_pb, float* __restrict__ bias_out)
{
    __shared__ float w[PDIM * HEADS];
    __shared__ float bb[HEADS];
    const int tid = threadIdx.x;
    for (int i = tid; i < PDIM * HEADS; i += 256) w[i] = w_pb[i];
    if (tid < HEADS) bb[tid] = b_pb[tid];
    __syncthreads();

    const int warp = (blockIdx.x << 3) + (tid >> 5);
    const int lane = tid & 31;
    const int q = warp >> 8;
    const int k = warp & 255;

    float4 p = *(const float4*)(pair + ((size_t)(q << 8) + k) * PDIM + (lane << 2));
    const int p0 = lane << 2;

    float res[HEADS];
#pragma unroll
    for (int h = 0; h < HEADS; h++) {
        float s = p.x * w[(p0 + 0) * HEADS + h]
                + p.y * w[(p0 + 1) * HEADS + h]
                + p.z * w[(p0 + 2) * HEADS + h]
                + p.w * w[(p0 + 3) * HEADS + h];
#pragma unroll
        for (int off = 16; off; off >>= 1)
            s += __shfl_xor_sync(0xFFFFFFFFu, s, off);
        res[h] = s + bb[h];
    }
    if (lane == 0) {
#pragma unroll
        for (int h = 0; h < HEADS; h++)
            bias_out[((size_t)(h << 8) + k) * LSEQ + q] = res[h];
    }
}

// ---------------------------------------------------------------------------
// Attention: one block per (n,h); K/V fp32 in smem; packed f32x2 math.
// Reads fp16 qkv, writes fp16 attention output.
// ---------------------------------------------------------------------------
__global__ void __launch_bounds__(256) attn_kernel(
    const int* __restrict__ mask, const __half* __restrict__ qkv,
    const float* __restrict__ bias, __half* __restrict__ outh)
{
    extern __shared__ float smf[];
    float* Ks = smf;                 // 256 rows x 32 floats
    float* Vs = smf + 8192;
    int* smask = (int*)(smf + 16384);

    const int n = blockIdx.x >> 3;
    const int h = blockIdx.x & 7;
    const int tid = threadIdx.x;

    const __half* basep = qkv + (size_t)(n * LSEQ) * 768 + h * DHEAD;

    for (int u = tid; u < 1024; u += 256) {
        const int l = u >> 2, uu = u & 3;
        uint4 kb = *(const uint4*)(basep + (size_t)l * 768 + 256 + uu * 8);
        uint4 vb = *(const uint4*)(basep + (size_t)l * 768 + 512 + uu * 8);
        const __half2* kp = (const __half2*)&kb;
        const __half2* vp = (const __half2*)&vb;
        float2* kd = (float2*)&Ks[l * 32 + uu * 8];
        float2* vd = (float2*)&Vs[l * 32 + uu * 8];
#pragma unroll
        for (int i = 0; i < 4; i++) { kd[i] = __half22float2(kp[i]); vd[i] = __half22float2(vp[i]); }
    }
    smask[tid] = mask[n * LSEQ + tid];
    __syncthreads();

    const int q = tid;
    unsigned long long q2[16];
    {
        const __half2* qp = (const __half2*)(basep + (size_t)q * 768);
#pragma unroll
        for (int i = 0; i < 16; i++) {
            float2 f = __half22float2(qp[i]);
            q2[i] = pk2(f.x, f.y);
        }
    }

    const float scale = 0.17677669529663687f;  // 1/sqrt(32)
    float m = -1e30f, lsum = 0.f;
    unsigned long long o2[16];
#pragma unroll
    for (int i = 0; i < 16; i++) o2[i] = 0ull;

    const float* brow = bias + (size_t)h * LSEQ * LSEQ + q;  // [h][k][q]

    for (int k = 0; k < LSEQ; k++) {
        if (smask[k] == 0) continue;
        const unsigned long long* krow = (const unsigned long long*)&Ks[k * 32];
        unsigned long long a0 = 0ull, a1 = 0ull, a2 = 0ull, a3 = 0ull;
#pragma unroll
        for (int i = 0; i < 4; i++) {
            a0 = fma2(q2[4 * i + 0], krow[4 * i + 0], a0);
            a1 = fma2(q2[4 * i + 1], krow[4 * i + 1], a1);
            a2 = fma2(q2[4 * i + 2], krow[4 * i + 2], a2);
            a3 = fma2(q2[4 * i + 3], krow[4 * i + 3], a3);
        }
        float2 f0 = upk2(a0), f1 = upk2(a1), f2 = upk2(a2), f3 = upk2(a3);
        float s = ((f0.x + f0.y) + (f1.x + f1.y)) + ((f2.x + f2.y) + (f3.x + f3.y));
        s = fmaf(s, scale, brow[(size_t)k * LSEQ]);

        const unsigned long long* vrow = (const unsigned long long*)&Vs[k * 32];
        if (s <= m) {
            const float p = __expf(s - m);
            lsum += p;
            const unsigned long long p2 = pk2(p, p);
#pragma unroll
            for (int i = 0; i < 16; i++) o2[i] = fma2(p2, vrow[i], o2[i]);
        } else {
            const float r = __expf(m - s);
            lsum = fmaf(lsum, r, 1.0f);
            const unsigned long long r2 = pk2(r, r);
#pragma unroll
            for (int i = 0; i < 16; i++) o2[i] = fma2(o2[i], r2, vrow[i]);
            m = s;
        }
    }

    const float inv = (lsum > 0.f) ? (1.0f / lsum) : 0.f;
    uint32_t hh[16];
#pragma unroll
    for (int i = 0; i < 16; i++) {
        float2 f = upk2(o2[i]);
        __half2 hv = __floats2half2_rn(f.x * inv, f.y * inv);
        hh[i] = *(uint32_t*)&hv;
    }
    uint4* dst = (uint4*)(outh + (size_t)(n * LSEQ + q) * DMODEL + h * DHEAD);
#pragma unroll
    for (int t = 0; t < 4; t++) dst[t] = ((uint4*)hh)[t];
}

// ---------------------------------------------------------------------------
// Launch
// ---------------------------------------------------------------------------
extern "C" void kernel_launch(void* const* d_in, const int* in_sizes, int n_in,
                              void* d_out, int out_size)
{
    const float* msa   = (const float*)d_in[0];
    const float* pair  = (const float*)d_in[1];
    const int*   mask  = (const int*)d_in[2];
    const float* w_qkv = (const float*)d_in[3];
    const float* w_pb  = (const float*)d_in[4];
    const float* b_pb  = (const float*)d_in[5];
    const float* w_out = (const float*)d_in[6];
    const float* b_out = (const float*)d_in[7];
    float* out = (float*)d_out;

    __half *msa_h, *wqkv_t, *wout_t, *qkv_h, *att_h;
    float* bias_ptr;
    cudaGetSymbolAddress((void**)&msa_h,   g_msa_h);
    cudaGetSymbolAddress((void**)&wqkv_t,  g_wqkv_t);
    cudaGetSymbolAddress((void**)&wout_t,  g_wout_t);
    cudaGetSymbolAddress((void**)&qkv_h,   g_qkv_h);
    cudaGetSymbolAddress((void**)&att_h,   g_att_h);
    cudaGetSymbolAddress((void**)&bias_ptr, g_bias);

    const int gemm_smem = 128 * 256 * 2 * 2;  // 131072
    cudaFuncSetAttribute(gemm_hmma<false>, cudaFuncAttributeMaxDynamicSharedMemorySize, gemm_smem);
    cudaFuncSetAttribute(gemm_hmma<true>,  cudaFuncAttributeMaxDynamicSharedMemorySize, gemm_smem);
    const int attn_smem = 16384 * 4 + 1024;
    cudaFuncSetAttribute(attn_kernel, cudaFuncAttributeMaxDynamicSharedMemorySize, attn_smem);

    // 0) fp16 conversions
    cvt_msa_kernel<<<2048, 512>>>((const float4*)msa, (__half2*)msa_h, MROWS * DMODEL / 4);
    cvt_wT_kernel<<<(3 * DMODEL * DMODEL + 255) / 256, 256>>>(w_qkv, wqkv_t, DMODEL, 3 * DMODEL);
    cvt_wT_kernel<<<(DMODEL * DMODEL + 255) / 256, 256>>>(w_out, wout_t, DMODEL, DMODEL);

    // 1) QKV = msa @ w_qkv  (HMMA fp16)
    gemm_hmma<false><<<dim3(6, 256), 256, gemm_smem>>>(msa_h, wqkv_t, qkv_h, nullptr, nullptr, 768);

    // 2) pair bias
    pair_bias_kernel<<<8192, 256>>>(pair, w_pb, b_pb, bias_ptr);

    // 3) attention
    attn_kernel<<<NSEQ * HEADS, 256, attn_smem>>>(mask, qkv_h, bias_ptr, att_h);

    // 4) out = att @ w_out + b_out  (HMMA fp16 -> fp32)
    gemm_hmma<true><<<dim3(2, 256), 256, gemm_smem>>>(att_h, wout_t, nullptr, out, b_out, 256);
}

// round 6
// speedup vs baseline: 2.3839x; 1.1603x over previous
#include <cuda_runtime.h>
#include <cuda_fp16.h>
#include <cstdint>

#define LSEQ   256
#define NSEQ   128
#define DMODEL 256
#define HEADS  8
#define DHEAD  32
#define PDIM   128
#define MROWS  (NSEQ * LSEQ)   // 32768

// ---------------------------------------------------------------------------
// Scratch (device globals; allocation-free, graph-capture safe)
// ---------------------------------------------------------------------------
__device__ __align__(16) __half g_msa_h[MROWS * DMODEL];        // fp16 msa [32768][256]
__device__ __align__(16) __half g_wqkv_t[3 * DMODEL * DMODEL];  // [768][256]  (N-major, K contiguous)
__device__ __align__(16) __half g_wout_t[DMODEL * DMODEL];      // [256][256]
__device__ __align__(16) __half g_qkv_h[MROWS * 3 * DMODEL];    // [32768][768]
__device__ __align__(16) __half g_att_h[MROWS * DMODEL];        // [32768][256]
__device__ float g_bias[HEADS * LSEQ * LSEQ];                   // [h][k][q]

// ---------------------------------------------------------------------------
// helpers
// ---------------------------------------------------------------------------
__device__ __forceinline__ uint32_t smem_u32(const void* p) {
    uint32_t a;
    asm("{ .reg .u64 t; cvta.to.shared.u64 t, %1; cvt.u32.u64 %0, t; }" : "=r"(a) : "l"(p));
    return a;
}

#define LDMX4(r0, r1, r2, r3, addr)                                           \
    asm volatile("ldmatrix.sync.aligned.m8n8.x4.shared.b16 {%0,%1,%2,%3}, [%4];" \
                 : "=r"(r0), "=r"(r1), "=r"(r2), "=r"(r3) : "r"(addr))

__device__ __forceinline__ void mma16816(float* c, const uint32_t* a, const uint32_t* b) {
    asm volatile("mma.sync.aligned.m16n8k16.row.col.f32.f16.f16.f32 "
                 "{%0,%1,%2,%3}, {%4,%5,%6,%7}, {%8,%9}, {%0,%1,%2,%3};"
                 : "+f"(c[0]), "+f"(c[1]), "+f"(c[2]), "+f"(c[3])
                 : "r"(a[0]), "r"(a[1]), "r"(a[2]), "r"(a[3]), "r"(b[0]), "r"(b[1]));
}

#define CP_ASYNC16(dst, src) \
    asm volatile("cp.async.cg.shared.global [%0], [%1], 16;" :: "r"(dst), "l"(src))
#define CP_COMMIT() asm volatile("cp.async.commit_group;" ::: "memory")
#define CP_WAIT(n)  asm volatile("cp.async.wait_group %0;" :: "n"(n) : "memory")

// packed f32x2
__device__ __forceinline__ unsigned long long pk2(float x, float y) {
    unsigned long long r;
    asm("mov.b64 %0, {%1, %2};" : "=l"(r) : "f"(x), "f"(y));
    return r;
}
__device__ __forceinline__ float2 upk2(unsigned long long v) {
    float2 r;
    asm("mov.b64 {%0, %1}, %2;" : "=f"(r.x), "=f"(r.y) : "l"(v));
    return r;
}
__device__ __forceinline__ unsigned long long fma2(unsigned long long a, unsigned long long b,
                                                   unsigned long long c) {
    unsigned long long d;
    asm("fma.rn.f32x2 %0, %1, %2, %3;" : "=l"(d) : "l"(a), "l"(b), "l"(c));
    return d;
}

// ---------------------------------------------------------------------------
// HMMA GEMM, cp.async 3-stage pipeline: C[M,N] = A[M,256] @ Bt[N,256]^T.
// Block tile 128x128; K chunked by 64 (4 chunks, 3 smem stages of 32KB).
// 8 warps each 32(M)x64(N), mma.sync m16n8k16, XOR-swizzled smem.
// ---------------------------------------------------------------------------
template <bool FINAL>
__global__ void __launch_bounds__(256) gemm_hmma(
    const __half* __restrict__ A, const __half* __restrict__ Bt,
    __half* __restrict__ Ch, float* __restrict__ Cf,
    const float* __restrict__ bias, int ldc)
{
    extern __shared__ __align__(16) char sm[];  // 3 stages x (A 16KB + B 16KB)

    const int tid = threadIdx.x;
    const int wid = tid >> 5, lane = tid & 31;
    const int m0 = blockIdx.y << 7;
    const int n0 = blockIdx.x << 7;
    const uint32_t smbase = smem_u32(sm);

    // ---- stage loader: chunk kc (64 k-cols) -> stage s
    auto load_stage = [&](int s, int kc) {
        const uint32_t base = smbase + s * 32768;
#pragma unroll
        for (int i = 0; i < 8; i++) {
            const int idx = tid + i * 256;       // 0..2047
            const int isB = idx >> 10;
            const int j = idx & 1023;
            const int r = j >> 3, c = j & 7;
            const __half* src = (isB ? Bt + (size_t)(n0 + r) * 256
                                     : A + (size_t)(m0 + r) * 256) + kc * 64 + c * 8;
            const uint32_t dst = base + isB * 16384 + r * 128 + ((c ^ (r & 7)) << 4);
            CP_ASYNC16(dst, src);
        }
        CP_COMMIT();
    };

    // ---- per-lane ldmatrix address components
    const int wm = (wid >> 1) * 32;
    const int wn = (wid & 1) * 64;
    const int a_row = (lane & 7) + ((lane >> 3) & 1) * 8;
    const int a_cadd = lane >> 4;
    const int b_row = (lane & 7) + ((lane >> 4) & 1) * 8;
    const int b_cadd = (lane >> 3) & 1;

    int a_r[2], b_r[4];
#pragma unroll
    for (int i = 0; i < 2; i++) a_r[i] = wm + 16 * i + a_row;
#pragma unroll
    for (int j = 0; j < 4; j++) b_r[j] = wn + 16 * j + b_row;

    float acc[2][8][4];
#pragma unroll
    for (int i = 0; i < 2; i++)
#pragma unroll
        for (int j = 0; j < 8; j++)
#pragma unroll
            for (int t = 0; t < 4; t++) acc[i][j][t] = 0.f;

    auto compute_chunk = [&](int s) {
        const uint32_t baseA = smbase + s * 32768;
        const uint32_t baseB = baseA + 16384;
#pragma unroll
        for (int kk = 0; kk < 4; kk++) {
            const int k8 = kk * 2;
            uint32_t a[2][4];
#pragma unroll
            for (int i = 0; i < 2; i++) {
                const uint32_t addr = baseA + a_r[i] * 128 +
                                      (((k8 + a_cadd) ^ (a_r[i] & 7)) << 4);
                LDMX4(a[i][0], a[i][1], a[i][2], a[i][3], addr);
            }
            uint32_t b[8][2];
#pragma unroll
            for (int j = 0; j < 4; j++) {
                const uint32_t addr = baseB + b_r[j] * 128 +
                                      (((k8 + b_cadd) ^ (b_r[j] & 7)) << 4);
                LDMX4(b[2 * j][0], b[2 * j][1], b[2 * j + 1][0], b[2 * j + 1][1], addr);
            }
#pragma unroll
            for (int i = 0; i < 2; i++)
#pragma unroll
                for (int j = 0; j < 8; j++)
                    mma16816(acc[i][j], a[i], b[j]);
        }
    };

    // ---- pipeline: chunks 0,1,2 -> stages 0,1,2; chunk 3 -> stage 0
    load_stage(0, 0);
    load_stage(1, 1);
    load_stage(2, 2);

    CP_WAIT(2); __syncthreads();
    compute_chunk(0);
    __syncthreads();           // everyone done reading stage 0
    load_stage(0, 3);

    CP_WAIT(2); __syncthreads();
    compute_chunk(1);

    CP_WAIT(1); __syncthreads();
    compute_chunk(2);

    CP_WAIT(0); __syncthreads();
    compute_chunk(0);

    // ---- epilogue
    const int tr = lane >> 2;
    const int tc = (lane & 3) * 2;
#pragma unroll
    for (int i = 0; i < 2; i++) {
        const int row = m0 + wm + 16 * i + tr;
#pragma unroll
        for (int j = 0; j < 8; j++) {
            const int col = n0 + wn + 8 * j + tc;
            if (FINAL) {
                const float b0 = __ldg(&bias[col]), b1 = __ldg(&bias[col + 1]);
                float2 v0 = make_float2(acc[i][j][0] + b0, acc[i][j][1] + b1);
                float2 v1 = make_float2(acc[i][j][2] + b0, acc[i][j][3] + b1);
                *(float2*)(Cf + (size_t)row * ldc + col) = v0;
                *(float2*)(Cf + (size_t)(row + 8) * ldc + col) = v1;
            } else {
                __half2 h0 = __floats2half2_rn(acc[i][j][0], acc[i][j][1]);
                __half2 h1 = __floats2half2_rn(acc[i][j][2], acc[i][j][3]);
                *(__half2*)(Ch + (size_t)row * ldc + col) = h0;
                *(__half2*)(Ch + (size_t)(row + 8) * ldc + col) = h1;
            }
        }
    }
}

// ---------------------------------------------------------------------------
// fp32 -> fp16 bulk convert
// ---------------------------------------------------------------------------
__global__ void __launch_bounds__(512) cvt_msa_kernel(const float4* __restrict__ in,
                                                      __half2* __restrict__ out, int n4)
{
    for (int i = blockIdx.x * 512 + threadIdx.x; i < n4; i += gridDim.x * 512) {
        float4 v = in[i];
        out[2 * i]     = __floats2half2_rn(v.x, v.y);
        out[2 * i + 1] = __floats2half2_rn(v.z, v.w);
    }
}

// transpose + convert: out[n*K + k] = in[k*N + n]
__global__ void __launch_bounds__(256) cvt_wT_kernel(const float* __restrict__ in,
                                                     __half* __restrict__ out, int K, int N)
{
    int idx = blockIdx.x * 256 + threadIdx.x;
    if (idx < N * K) {
        int n = idx / K, k = idx - n * K;
        out[idx] = __float2half(in[k * N + n]);
    }
}

// ---------------------------------------------------------------------------
// pair_bias: bias[h][k][q] = sum_p pair[q][k][p] * w_pb[p][h] + b_pb[h]
// ---------------------------------------------------------------------------
__global__ void __launch_bounds__(256) pair_bias_kernel(
    const float* __restrict__ pair, const float* __restrict__ w_pb,
    const float* __restrict__ b_pb, float* __restrict__ bias_out)
{
    __shared__ float w[PDIM * HEADS];
    __shared__ float bb[HEADS];
    const int tid = threadIdx.x;
    for (int i = tid; i < PDIM * HEADS; i += 256) w[i] = w_pb[i];
    if (tid < HEADS) bb[tid] = b_pb[tid];
    __syncthreads();

    const int warp = (blockIdx.x << 3) + (tid >> 5);
    const int lane = tid & 31;
    const int q = warp >> 8;
    const int k = warp & 255;

    float4 p = *(const float4*)(pair + ((size_t)(q << 8) + k) * PDIM + (lane << 2));
    const int p0 = lane << 2;

    float res[HEADS];
#pragma unroll
    for (int h = 0; h < HEADS; h++) {
        float s = p.x * w[(p0 + 0) * HEADS + h]
                + p.y * w[(p0 + 1) * HEADS + h]
                + p.z * w[(p0 + 2) * HEADS + h]
                + p.w * w[(p0 + 3) * HEADS + h];
#pragma unroll
        for (int off = 16; off; off >>= 1)
            s += __shfl_xor_sync(0xFFFFFFFFu, s, off);
        res[h] = s + bb[h];
    }
    if (lane == 0) {
#pragma unroll
        for (int h = 0; h < HEADS; h++)
            bias_out[((size_t)(h << 8) + k) * LSEQ + q] = res[h];
    }
}

// ---------------------------------------------------------------------------
// Attention v2: one block per (n,h). Branchless softmax (no max tracking —
// scores are bounded; fminf(60) guards overflow; softmax is shift-invariant).
// K/V fp32 in smem via LDS.128; bias slice staged through smem in 32-row
// chunks (coalesced). packed f32x2 math.
// ---------------------------------------------------------------------------
__global__ void __launch_bounds__(256) attn_kernel(
    const int* __restrict__ mask, const __half* __restrict__ qkv,
    const float* __restrict__ bias, __half* __restrict__ outh)
{
    extern __shared__ float smf[];
    float* Ks = smf;                  // [256][32]
    float* Vs = smf + 8192;           // [256][32]
    float* Bsm = smf + 16384;         // [32][256] bias chunk
    int* smask = (int*)(smf + 24576);

    const int n = blockIdx.x >> 3;
    const int h = blockIdx.x & 7;
    const int tid = threadIdx.x;

    const __half* basep = qkv + (size_t)(n * LSEQ) * 768 + h * DHEAD;

    for (int u = tid; u < 1024; u += 256) {
        const int l = u >> 2, uu = u & 3;
        uint4 kb = *(const uint4*)(basep + (size_t)l * 768 + 256 + uu * 8);
        uint4 vb = *(const uint4*)(basep + (size_t)l * 768 + 512 + uu * 8);
        const __half2* kp = (const __half2*)&kb;
        const __half2* vp = (const __half2*)&vb;
        float2* kd = (float2*)&Ks[l * 32 + uu * 8];
        float2* vd = (float2*)&Vs[l * 32 + uu * 8];
#pragma unroll
        for (int i = 0; i < 4; i++) { kd[i] = __half22float2(kp[i]); vd[i] = __half22float2(vp[i]); }
    }
    smask[tid] = mask[n * LSEQ + tid];

    const int q = tid;
    const float scale = 0.17677669529663687f;  // 1/sqrt(32)
    unsigned long long q2[16];
    {
        const __half2* qp = (const __half2*)(basep + (size_t)q * 768);
#pragma unroll
        for (int i = 0; i < 16; i++) {
            float2 f = __half22float2(qp[i]);
            q2[i] = pk2(f.x * scale, f.y * scale);
        }
    }

    float lsum = 0.f;
    unsigned long long o2[16];
#pragma unroll
    for (int i = 0; i < 16; i++) o2[i] = 0ull;

    const float* bslice = bias + (size_t)h * LSEQ * LSEQ;  // [k][q]

    for (int kc = 0; kc < 8; kc++) {
        __syncthreads();
        // stage 32 bias rows (32x256 fp32 = 32KB), coalesced
        const float4* bsrc = (const float4*)(bslice + kc * 32 * LSEQ);
        float4* bdst = (float4*)Bsm;
#pragma unroll
        for (int i = 0; i < 8; i++) bdst[tid + i * 256] = bsrc[tid + i * 256];
        __syncthreads();

#pragma unroll 4
        for (int kk = 0; kk < 32; kk++) {
            const int k = kc * 32 + kk;
            if (smask[k] == 0) continue;

            const float4* k4 = (const float4*)&Ks[k * 32];
            unsigned long long a0 = 0ull, a1 = 0ull, a2 = 0ull, a3 = 0ull;
#pragma unroll
            for (int i = 0; i < 2; i++) {
                float4 ka = k4[4 * i + 0], kb = k4[4 * i + 1];
                float4 kc2 = k4[4 * i + 2], kd = k4[4 * i + 3];
                a0 = fma2(q2[8 * i + 0], pk2(ka.x, ka.y), a0);
                a1 = fma2(q2[8 * i + 1], pk2(ka.z, ka.w), a1);
                a2 = fma2(q2[8 * i + 2], pk2(kb.x, kb.y), a2);
                a3 = fma2(q2[8 * i + 3], pk2(kb.z, kb.w), a3);
                a0 = fma2(q2[8 * i + 4], pk2(kc2.x, kc2.y), a0);
                a1 = fma2(q2[8 * i + 5], pk2(kc2.z, kc2.w), a1);
                a2 = fma2(q2[8 * i + 6], pk2(kd.x, kd.y), a2);
                a3 = fma2(q2[8 * i + 7], pk2(kd.z, kd.w), a3);
            }
            float2 f0 = upk2(a0), f1 = upk2(a1), f2 = upk2(a2), f3 = upk2(a3);
            float s = ((f0.x + f0.y) + (f1.x + f1.y)) + ((f2.x + f2.y) + (f3.x + f3.y));
            s = fminf(s + Bsm[kk * 256 + q], 60.f);
            const float p = __expf(s);
            lsum += p;

            const unsigned long long p2 = pk2(p, p);
            const float4* v4 = (const float4*)&Vs[k * 32];
#pragma unroll
            for (int j = 0; j < 8; j++) {
                float4 vv = v4[j];
                o2[2 * j]     = fma2(p2, pk2(vv.x, vv.y), o2[2 * j]);
                o2[2 * j + 1] = fma2(p2, pk2(vv.z, vv.w), o2[2 * j + 1]);
            }
        }
    }

    const float inv = (lsum > 0.f) ? (1.0f / lsum) : 0.f;
    uint32_t hh[16];
#pragma unroll
    for (int i = 0; i < 16; i++) {
        float2 f = upk2(o2[i]);
        __half2 hv = __floats2half2_rn(f.x * inv, f.y * inv);
        hh[i] = *(uint32_t*)&hv;
    }
    uint4* dst = (uint4*)(outh + (size_t)(n * LSEQ + q) * DMODEL + h * DHEAD);
#pragma unroll
    for (int t = 0; t < 4; t++) dst[t] = ((uint4*)hh)[t];
}

// ---------------------------------------------------------------------------
// Launch
// ---------------------------------------------------------------------------
extern "C" void kernel_launch(void* const* d_in, const int* in_sizes, int n_in,
                              void* d_out, int out_size)
{
    const float* msa   = (const float*)d_in[0];
    const float* pair  = (const float*)d_in[1];
    const int*   mask  = (const int*)d_in[2];
    const float* w_qkv = (const float*)d_in[3];
    const float* w_pb  = (const float*)d_in[4];
    const float* b_pb  = (const float*)d_in[5];
    const float* w_out = (const float*)d_in[6];
    const float* b_out = (const float*)d_in[7];
    float* out = (float*)d_out;

    __half *msa_h, *wqkv_t, *wout_t, *qkv_h, *att_h;
    float* bias_ptr;
    cudaGetSymbolAddress((void**)&msa_h,   g_msa_h);
    cudaGetSymbolAddress((void**)&wqkv_t,  g_wqkv_t);
    cudaGetSymbolAddress((void**)&wout_t,  g_wout_t);
    cudaGetSymbolAddress((void**)&qkv_h,   g_qkv_h);
    cudaGetSymbolAddress((void**)&att_h,   g_att_h);
    cudaGetSymbolAddress((void**)&bias_ptr, g_bias);

    const int gemm_smem = 3 * 32768;  // 96KB (3 stages)
    cudaFuncSetAttribute(gemm_hmma<false>, cudaFuncAttributeMaxDynamicSharedMemorySize, gemm_smem);
    cudaFuncSetAttribute(gemm_hmma<true>,  cudaFuncAttributeMaxDynamicSharedMemorySize, gemm_smem);
    const int attn_smem = (8192 * 3 + 256) * 4;  // K,V,bias-chunk,mask = 99328
    cudaFuncSetAttribute(attn_kernel, cudaFuncAttributeMaxDynamicSharedMemorySize, attn_smem);

    // 0) fp16 conversions
    cvt_msa_kernel<<<2048, 512>>>((const float4*)msa, (__half2*)msa_h, MROWS * DMODEL / 4);
    cvt_wT_kernel<<<(3 * DMODEL * DMODEL + 255) / 256, 256>>>(w_qkv, wqkv_t, DMODEL, 3 * DMODEL);
    cvt_wT_kernel<<<(DMODEL * DMODEL + 255) / 256, 256>>>(w_out, wout_t, DMODEL, DMODEL);

    // 1) QKV = msa @ w_qkv  (HMMA fp16, pipelined)
    gemm_hmma<false><<<dim3(6, 256), 256, gemm_smem>>>(msa_h, wqkv_t, qkv_h, nullptr, nullptr, 768);

    // 2) pair bias
    pair_bias_kernel<<<8192, 256>>>(pair, w_pb, b_pb, bias_ptr);

    // 3) attention
    attn_kernel<<<NSEQ * HEADS, 256, attn_smem>>>(mask, qkv_h, bias_ptr, att_h);

    // 4) out = att @ w_out + b_out  (HMMA fp16 -> fp32, pipelined)
    gemm_hmma<true><<<dim3(2, 256), 256, gemm_smem>>>(att_h, wout_t, nullptr, out, b_out, 256);
}

// round 7
// speedup vs baseline: 3.2785x; 1.3752x over previous
#include <cuda_runtime.h>
#include <cuda_fp16.h>
#include <cstdint>

#define LSEQ   256
#define NSEQ   128
#define DMODEL 256
#define HEADS  8
#define DHEAD  32
#define PDIM   128
#define MROWS  (NSEQ * LSEQ)   // 32768

// ---------------------------------------------------------------------------
// Scratch (device globals; allocation-free, graph-capture safe)
// ---------------------------------------------------------------------------
__device__ __align__(16) __half g_msa_h[MROWS * DMODEL];        // fp16 msa [32768][256]
__device__ __align__(16) __half g_wqkv_t[3 * DMODEL * DMODEL];  // [768][256]  (N-major, K contiguous)
__device__ __align__(16) __half g_wout_t[DMODEL * DMODEL];      // [256][256]
__device__ __align__(16) __half g_qkv_h[MROWS * 3 * DMODEL];    // [32768][768]
__device__ __align__(16) __half g_att_h[MROWS * DMODEL];        // [32768][256]
__device__ float g_bias[HEADS * LSEQ * LSEQ];                   // [h][q][k]

// ---------------------------------------------------------------------------
// helpers
// ---------------------------------------------------------------------------
__device__ __forceinline__ uint32_t smem_u32(const void* p) {
    uint32_t a;
    asm("{ .reg .u64 t; cvta.to.shared.u64 t, %1; cvt.u32.u64 %0, t; }" : "=r"(a) : "l"(p));
    return a;
}

#define LDMX4(r0, r1, r2, r3, addr)                                           \
    asm volatile("ldmatrix.sync.aligned.m8n8.x4.shared.b16 {%0,%1,%2,%3}, [%4];" \
                 : "=r"(r0), "=r"(r1), "=r"(r2), "=r"(r3) : "r"(addr))

#define LDMX4T(r0, r1, r2, r3, addr)                                          \
    asm volatile("ldmatrix.sync.aligned.m8n8.x4.trans.shared.b16 {%0,%1,%2,%3}, [%4];" \
                 : "=r"(r0), "=r"(r1), "=r"(r2), "=r"(r3) : "r"(addr))

__device__ __forceinline__ void mma16816(float* c, const uint32_t* a, const uint32_t* b) {
    asm volatile("mma.sync.aligned.m16n8k16.row.col.f32.f16.f16.f32 "
                 "{%0,%1,%2,%3}, {%4,%5,%6,%7}, {%8,%9}, {%0,%1,%2,%3};"
                 : "+f"(c[0]), "+f"(c[1]), "+f"(c[2]), "+f"(c[3])
                 : "r"(a[0]), "r"(a[1]), "r"(a[2]), "r"(a[3]), "r"(b[0]), "r"(b[1]));
}

#define CP_ASYNC16(dst, src) \
    asm volatile("cp.async.cg.shared.global [%0], [%1], 16;" :: "r"(dst), "l"(src))
#define CP_COMMIT() asm volatile("cp.async.commit_group;" ::: "memory")
#define CP_WAIT(n)  asm volatile("cp.async.wait_group %0;" :: "n"(n) : "memory")

// ---------------------------------------------------------------------------
// HMMA GEMM, cp.async 3-stage pipeline: C[M,N] = A[M,256] @ Bt[N,256]^T.
// ---------------------------------------------------------------------------
template <bool FINAL>
__global__ void __launch_bounds__(256) gemm_hmma(
    const __half* __restrict__ A, const __half* __restrict__ Bt,
    __half* __restrict__ Ch, float* __restrict__ Cf,
    const float* __restrict__ bias, int ldc)
{
    extern __shared__ __align__(16) char sm[];  // 3 stages x (A 16KB + B 16KB)

    const int tid = threadIdx.x;
    const int wid = tid >> 5, lane = tid & 31;
    const int m0 = blockIdx.y << 7;
    const int n0 = blockIdx.x << 7;
    const uint32_t smbase = smem_u32(sm);

    auto load_stage = [&](int s, int kc) {
        const uint32_t base = smbase + s * 32768;
#pragma unroll
        for (int i = 0; i < 8; i++) {
            const int idx = tid + i * 256;
            const int isB = idx >> 10;
            const int j = idx & 1023;
            const int r = j >> 3, c = j & 7;
            const __half* src = (isB ? Bt + (size_t)(n0 + r) * 256
                                     : A + (size_t)(m0 + r) * 256) + kc * 64 + c * 8;
            const uint32_t dst = base + isB * 16384 + r * 128 + ((c ^ (r & 7)) << 4);
            CP_ASYNC16(dst, src);
        }
        CP_COMMIT();
    };

    const int wm = (wid >> 1) * 32;
    const int wn = (wid & 1) * 64;
    const int a_row = (lane & 7) + ((lane >> 3) & 1) * 8;
    const int a_cadd = lane >> 4;
    const int b_row = (lane & 7) + ((lane >> 4) & 1) * 8;
    const int b_cadd = (lane >> 3) & 1;

    int a_r[2], b_r[4];
#pragma unroll
    for (int i = 0; i < 2; i++) a_r[i] = wm + 16 * i + a_row;
#pragma unroll
    for (int j = 0; j < 4; j++) b_r[j] = wn + 16 * j + b_row;

    float acc[2][8][4];
#pragma unroll
    for (int i = 0; i < 2; i++)
#pragma unroll
        for (int j = 0; j < 8; j++)
#pragma unroll
            for (int t = 0; t < 4; t++) acc[i][j][t] = 0.f;

    auto compute_chunk = [&](int s) {
        const uint32_t baseA = smbase + s * 32768;
        const uint32_t baseB = baseA + 16384;
#pragma unroll
        for (int kk = 0; kk < 4; kk++) {
            const int k8 = kk * 2;
            uint32_t a[2][4];
#pragma unroll
            for (int i = 0; i < 2; i++) {
                const uint32_t addr = baseA + a_r[i] * 128 +
                                      (((k8 + a_cadd) ^ (a_r[i] & 7)) << 4);
                LDMX4(a[i][0], a[i][1], a[i][2], a[i][3], addr);
            }
            uint32_t b[8][2];
#pragma unroll
            for (int j = 0; j < 4; j++) {
                const uint32_t addr = baseB + b_r[j] * 128 +
                                      (((k8 + b_cadd) ^ (b_r[j] & 7)) << 4);
                LDMX4(b[2 * j][0], b[2 * j][1], b[2 * j + 1][0], b[2 * j + 1][1], addr);
            }
#pragma unroll
            for (int i = 0; i < 2; i++)
#pragma unroll
                for (int j = 0; j < 8; j++)
                    mma16816(acc[i][j], a[i], b[j]);
        }
    };

    load_stage(0, 0);
    load_stage(1, 1);
    load_stage(2, 2);

    CP_WAIT(2); __syncthreads();
    compute_chunk(0);
    __syncthreads();
    load_stage(0, 3);

    CP_WAIT(2); __syncthreads();
    compute_chunk(1);

    CP_WAIT(1); __syncthreads();
    compute_chunk(2);

    CP_WAIT(0); __syncthreads();
    compute_chunk(0);

    const int tr = lane >> 2;
    const int tc = (lane & 3) * 2;
#pragma unroll
    for (int i = 0; i < 2; i++) {
        const int row = m0 + wm + 16 * i + tr;
#pragma unroll
        for (int j = 0; j < 8; j++) {
            const int col = n0 + wn + 8 * j + tc;
            if (FINAL) {
                const float b0 = __ldg(&bias[col]), b1 = __ldg(&bias[col + 1]);
                float2 v0 = make_float2(acc[i][j][0] + b0, acc[i][j][1] + b1);
                float2 v1 = make_float2(acc[i][j][2] + b0, acc[i][j][3] + b1);
                *(float2*)(Cf + (size_t)row * ldc + col) = v0;
                *(float2*)(Cf + (size_t)(row + 8) * ldc + col) = v1;
            } else {
                __half2 h0 = __floats2half2_rn(acc[i][j][0], acc[i][j][1]);
                __half2 h1 = __floats2half2_rn(acc[i][j][2], acc[i][j][3]);
                *(__half2*)(Ch + (size_t)row * ldc + col) = h0;
                *(__half2*)(Ch + (size_t)(row + 8) * ldc + col) = h1;
            }
        }
    }
}

// ---------------------------------------------------------------------------
// fp32 -> fp16 bulk convert
// ---------------------------------------------------------------------------
__global__ void __launch_bounds__(512) cvt_msa_kernel(const float4* __restrict__ in,
                                                      __half2* __restrict__ out, int n4)
{
    for (int i = blockIdx.x * 512 + threadIdx.x; i < n4; i += gridDim.x * 512) {
        float4 v = in[i];
        out[2 * i]     = __floats2half2_rn(v.x, v.y);
        out[2 * i + 1] = __floats2half2_rn(v.z, v.w);
    }
}

__global__ void __launch_bounds__(256) cvt_wT_kernel(const float* __restrict__ in,
                                                     __half* __restrict__ out, int K, int N)
{
    int idx = blockIdx.x * 256 + threadIdx.x;
    if (idx < N * K) {
        int n = idx / K, k = idx - n * K;
        out[idx] = __float2half(in[k * N + n]);
    }
}

// ---------------------------------------------------------------------------
// pair_bias: bias[h][q][k] = sum_p pair[q][k][p] * w_pb[p][h] + b_pb[h]
// ---------------------------------------------------------------------------
__global__ void __launch_bounds__(256) pair_bias_kernel(
    const float* __restrict__ pair, const float* __restrict__ w_pb,
    const float* __restrict__ b_pb, float* __restrict__ bias_out)
{
    __shared__ float w[PDIM * HEADS];
    __shared__ float bb[HEADS];
    const int tid = threadIdx.x;
    for (int i = tid; i < PDIM * HEADS; i += 256) w[i] = w_pb[i];
    if (tid < HEADS) bb[tid] = b_pb[tid];
    __syncthreads();

    const int warp = (blockIdx.x << 3) + (tid >> 5);
    const int lane = tid & 31;
    const int q = warp >> 8;
    const int k = warp & 255;

    float4 p = *(const float4*)(pair + ((size_t)(q << 8) + k) * PDIM + (lane << 2));
    const int p0 = lane << 2;

    float res[HEADS];
#pragma unroll
    for (int h = 0; h < HEADS; h++) {
        float s = p.x * w[(p0 + 0) * HEADS + h]
                + p.y * w[(p0 + 1) * HEADS + h]
                + p.z * w[(p0 + 2) * HEADS + h]
                + p.w * w[(p0 + 3) * HEADS + h];
#pragma unroll
        for (int off = 16; off; off >>= 1)
            s += __shfl_xor_sync(0xFFFFFFFFu, s, off);
        res[h] = s + bb[h];
    }
    if (lane == 0) {
#pragma unroll
        for (int h = 0; h < HEADS; h++)
            bias_out[((size_t)(h << 8) + q) * LSEQ + k] = res[h];
    }
}

// ---------------------------------------------------------------------------
// Attention v3: HMMA flash-attention. One CTA per (n,h), 8 warps x 32 q-rows.
// Q/K/V fp16 in smem (80B row pitch, ldmatrix conflict-free). Online softmax
// with masked-max; P packed in-register to fp16 A-fragments for PV.
// ---------------------------------------------------------------------------
__global__ void __launch_bounds__(256) attn_kernel(
    const int* __restrict__ mask, const __half* __restrict__ qkv,
    const float* __restrict__ bias, __half* __restrict__ outh)
{
    extern __shared__ __align__(16) __half smh[];
    __half* Qs = smh;               // 256 rows x 40 halfs (80B pitch)
    __half* Ks = smh + 10240;
    __half* Vs = smh + 20480;
    float* maskf = (float*)(smh + 30720);  // 256 floats

    const int n = blockIdx.x >> 3;
    const int h = blockIdx.x & 7;
    const int tid = threadIdx.x;
    const int wid = tid >> 5, lane = tid & 31;

    const __half* basep = qkv + (size_t)(n * LSEQ) * 768 + h * DHEAD;
    for (int u = tid; u < 1024; u += 256) {
        const int l = u >> 2, c = u & 3;
        const __half* r = basep + (size_t)l * 768 + c * 8;
        *(uint4*)&Qs[l * 40 + c * 8] = *(const uint4*)(r);
        *(uint4*)&Ks[l * 40 + c * 8] = *(const uint4*)(r + 256);
        *(uint4*)&Vs[l * 40 + c * 8] = *(const uint4*)(r + 512);
    }
    maskf[tid] = mask[n * LSEQ + tid] ? 1.0f : 0.0f;
    __syncthreads();

    const uint32_t Qa = smem_u32(Qs), Ka = smem_u32(Ks), Va = smem_u32(Vs);
    const int wq0 = wid * 32;
    const int a_row = (lane & 7) + ((lane >> 3) & 1) * 8;
    const int a_c = lane >> 4;
    const int b_row = (lane & 7) + ((lane >> 4) & 1) * 8;
    const int b_c = (lane >> 3) & 1;
    const int tr = lane >> 2, tc = (lane & 3) * 2;

    // Q fragments (persistent)
    uint32_t aq[2][2][4];
#pragma unroll
    for (int m = 0; m < 2; m++)
#pragma unroll
        for (int kt = 0; kt < 2; kt++) {
            const uint32_t addr = Qa + (wq0 + m * 16 + a_row) * 80 + (kt * 2 + a_c) * 16;
            LDMX4(aq[m][kt][0], aq[m][kt][1], aq[m][kt][2], aq[m][kt][3], addr);
        }

    float o[2][4][4];
#pragma unroll
    for (int m = 0; m < 2; m++)
#pragma unroll
        for (int nt = 0; nt < 4; nt++)
#pragma unroll
            for (int t = 0; t < 4; t++) o[m][nt][t] = 0.f;
    float rsum[2][2] = {{0.f, 0.f}, {0.f, 0.f}};
    float rmax[2][2] = {{-1e30f, -1e30f}, {-1e30f, -1e30f}};

    const float scale = 0.17677669529663687f;  // 1/sqrt(32)
    const float* bias_h = bias + (size_t)h * LSEQ * LSEQ;  // [q][k]

    for (int j = 0; j < 4; j++) {
        const int kb = j * 64;

        // K fragments
        uint32_t bk[4][2][4];
#pragma unroll
        for (int kg = 0; kg < 4; kg++)
#pragma unroll
            for (int kt = 0; kt < 2; kt++) {
                const uint32_t addr = Ka + (kb + kg * 16 + b_row) * 80 + (kt * 2 + b_c) * 16;
                LDMX4(bk[kg][kt][0], bk[kg][kt][1], bk[kg][kt][2], bk[kg][kt][3], addr);
            }

        // S = Q K^T
        float s[2][8][4];
#pragma unroll
        for (int m = 0; m < 2; m++)
#pragma unroll
            for (int nn = 0; nn < 8; nn++) {
#pragma unroll
                for (int t = 0; t < 4; t++) s[m][nn][t] = 0.f;
#pragma unroll
                for (int kt = 0; kt < 2; kt++)
                    mma16816(s[m][nn], aq[m][kt], &bk[nn >> 1][kt][(nn & 1) * 2]);
            }

        // scale + bias, masked running max
        float cmax[2][2] = {{-1e30f, -1e30f}, {-1e30f, -1e30f}};
#pragma unroll
        for (int m = 0; m < 2; m++) {
            const float* br0 = bias_h + (size_t)(wq0 + m * 16 + tr) * 256 + kb;
            const float* br1 = br0 + 8 * 256;
#pragma unroll
            for (int nn = 0; nn < 8; nn++) {
                const int kc = nn * 8 + tc;
                float2 mf = *(float2*)&maskf[kb + kc];
                float2 b0 = *(const float2*)(br0 + kc);
                float2 b1 = *(const float2*)(br1 + kc);
                float v0 = fmaf(s[m][nn][0], scale, b0.x);
                float v1 = fmaf(s[m][nn][1], scale, b0.y);
                float v2 = fmaf(s[m][nn][2], scale, b1.x);
                float v3 = fmaf(s[m][nn][3], scale, b1.y);
                s[m][nn][0] = v0; s[m][nn][1] = v1; s[m][nn][2] = v2; s[m][nn][3] = v3;
                cmax[m][0] = fmaxf(cmax[m][0], mf.x > 0.f ? v0 : -1e30f);
                cmax[m][0] = fmaxf(cmax[m][0], mf.y > 0.f ? v1 : -1e30f);
                cmax[m][1] = fmaxf(cmax[m][1], mf.x > 0.f ? v2 : -1e30f);
                cmax[m][1] = fmaxf(cmax[m][1], mf.y > 0.f ? v3 : -1e30f);
            }
        }

        // quad-reduce max, rescale running state
        float sf[2][2];
#pragma unroll
        for (int m = 0; m < 2; m++)
#pragma unroll
            for (int r = 0; r < 2; r++) {
                float v = cmax[m][r];
                v = fmaxf(v, __shfl_xor_sync(0xFFFFFFFFu, v, 1));
                v = fmaxf(v, __shfl_xor_sync(0xFFFFFFFFu, v, 2));
                const float mnew = fmaxf(rmax[m][r], v);
                sf[m][r] = __expf(rmax[m][r] - mnew);
                rmax[m][r] = mnew;
                rsum[m][r] *= sf[m][r];
            }
#pragma unroll
        for (int m = 0; m < 2; m++)
#pragma unroll
            for (int nt = 0; nt < 4; nt++) {
                o[m][nt][0] *= sf[m][0]; o[m][nt][1] *= sf[m][0];
                o[m][nt][2] *= sf[m][1]; o[m][nt][3] *= sf[m][1];
            }

        // exp + mask, pack P to fp16 A-fragments
        uint32_t ap[2][4][4];
#pragma unroll
        for (int m = 0; m < 2; m++)
#pragma unroll
            for (int nn = 0; nn < 8; nn++) {
                const int kc = nn * 8 + tc;
                float2 mf = *(float2*)&maskf[kb + kc];
                float p0 = __expf(fminf(s[m][nn][0] - rmax[m][0], 0.f)) * mf.x;
                float p1 = __expf(fminf(s[m][nn][1] - rmax[m][0], 0.f)) * mf.y;
                float p2 = __expf(fminf(s[m][nn][2] - rmax[m][1], 0.f)) * mf.x;
                float p3 = __expf(fminf(s[m][nn][3] - rmax[m][1], 0.f)) * mf.y;
                rsum[m][0] += p0 + p1;
                rsum[m][1] += p2 + p3;
                __half2 h01 = __floats2half2_rn(p0, p1);
                __half2 h23 = __floats2half2_rn(p2, p3);
                const int kt = nn >> 1, half_ = (nn & 1) * 2;
                ap[m][kt][half_ + 0] = *(uint32_t*)&h01;
                ap[m][kt][half_ + 1] = *(uint32_t*)&h23;
            }

        // V fragments (trans) — loaded late to keep register pressure down
        uint32_t bv[4][4][2];
#pragma unroll
        for (int kg = 0; kg < 4; kg++)
#pragma unroll
            for (int dh = 0; dh < 2; dh++) {
                uint32_t r0, r1, r2, r3;
                const uint32_t addr = Va + (kb + kg * 16 + a_row) * 80 + (dh * 2 + a_c) * 16;
                LDMX4T(r0, r1, r2, r3, addr);
                bv[kg][dh * 2][0] = r0;     bv[kg][dh * 2][1] = r1;
                bv[kg][dh * 2 + 1][0] = r2; bv[kg][dh * 2 + 1][1] = r3;
            }

        // O += P V
#pragma unroll
        for (int m = 0; m < 2; m++)
#pragma unroll
            for (int nt = 0; nt < 4; nt++)
#pragma unroll
                for (int kt = 0; kt < 4; kt++)
                    mma16816(o[m][nt], ap[m][kt], bv[kt][nt]);
    }

    // final row-sum reduce and normalize
    float inv[2][2];
#pragma unroll
    for (int m = 0; m < 2; m++)
#pragma unroll
        for (int r = 0; r < 2; r++) {
            float v = rsum[m][r];
            v += __shfl_xor_sync(0xFFFFFFFFu, v, 1);
            v += __shfl_xor_sync(0xFFFFFFFFu, v, 2);
            inv[m][r] = (v > 0.f) ? (1.0f / v) : 0.f;
        }

#pragma unroll
    for (int m = 0; m < 2; m++) {
        const size_t q0 = (size_t)(n * LSEQ + wq0 + m * 16 + tr);
        const int dcol = h * DHEAD + tc;
#pragma unroll
        for (int nt = 0; nt < 4; nt++) {
            __half2 h0 = __floats2half2_rn(o[m][nt][0] * inv[m][0], o[m][nt][1] * inv[m][0]);
            __half2 h1 = __floats2half2_rn(o[m][nt][2] * inv[m][1], o[m][nt][3] * inv[m][1]);
            *(__half2*)(outh + q0 * DMODEL + dcol + nt * 8) = h0;
            *(__half2*)(outh + (q0 + 8) * DMODEL + dcol + nt * 8) = h1;
        }
    }
}

// ---------------------------------------------------------------------------
// Launch
// ---------------------------------------------------------------------------
extern "C" void kernel_launch(void* const* d_in, const int* in_sizes, int n_in,
                              void* d_out, int out_size)
{
    const float* msa   = (const float*)d_in[0];
    const float* pair  = (const float*)d_in[1];
    const int*   mask  = (const int*)d_in[2];
    const float* w_qkv = (const float*)d_in[3];
    const float* w_pb  = (const float*)d_in[4];
    const float* b_pb  = (const float*)d_in[5];
    const float* w_out = (const float*)d_in[6];
    const float* b_out = (const float*)d_in[7];
    float* out = (float*)d_out;

    __half *msa_h, *wqkv_t, *wout_t, *qkv_h, *att_h;
    float* bias_ptr;
    cudaGetSymbolAddress((void**)&msa_h,   g_msa_h);
    cudaGetSymbolAddress((void**)&wqkv_t,  g_wqkv_t);
    cudaGetSymbolAddress((void**)&wout_t,  g_wout_t);
    cudaGetSymbolAddress((void**)&qkv_h,   g_qkv_h);
    cudaGetSymbolAddress((void**)&att_h,   g_att_h);
    cudaGetSymbolAddress((void**)&bias_ptr, g_bias);

    const int gemm_smem = 3 * 32768;  // 96KB
    cudaFuncSetAttribute(gemm_hmma<false>, cudaFuncAttributeMaxDynamicSharedMemorySize, gemm_smem);
    cudaFuncSetAttribute(gemm_hmma<true>,  cudaFuncAttributeMaxDynamicSharedMemorySize, gemm_smem);
    const int attn_smem = 30720 * 2 + 1024;  // QKV fp16 (80B pitch) + maskf = 62464
    cudaFuncSetAttribute(attn_kernel, cudaFuncAttributeMaxDynamicSharedMemorySize, attn_smem);

    // 0) fp16 conversions
    cvt_msa_kernel<<<2048, 512>>>((const float4*)msa, (__half2*)msa_h, MROWS * DMODEL / 4);
    cvt_wT_kernel<<<(3 * DMODEL * DMODEL + 255) / 256, 256>>>(w_qkv, wqkv_t, DMODEL, 3 * DMODEL);
    cvt_wT_kernel<<<(DMODEL * DMODEL + 255) / 256, 256>>>(w_out, wout_t, DMODEL, DMODEL);

    // 1) QKV = msa @ w_qkv  (HMMA fp16, pipelined)
    gemm_hmma<false><<<dim3(6, 256), 256, gemm_smem>>>(msa_h, wqkv_t, qkv_h, nullptr, nullptr, 768);

    // 2) pair bias -> [h][q][k]
    pair_bias_kernel<<<8192, 256>>>(pair, w_pb, b_pb, bias_ptr);

    // 3) attention (HMMA flash)
    attn_kernel<<<NSEQ * HEADS, 256, attn_smem>>>(mask, qkv_h, bias_ptr, att_h);

    // 4) out = att @ w_out + b_out  (HMMA fp16 -> fp32, pipelined)
    gemm_hmma<true><<<dim3(2, 256), 256, gemm_smem>>>(att_h, wout_t, nullptr, out, b_out, 256);
}

// round 8
// speedup vs baseline: 3.5042x; 1.0688x over previous
#include <cuda_runtime.h>
#include <cuda_fp16.h>
#include <cstdint>

#define LSEQ   256
#define NSEQ   128
#define DMODEL 256
#define HEADS  8
#define DHEAD  32
#define PDIM   128
#define MROWS  (NSEQ * LSEQ)   // 32768

// ---------------------------------------------------------------------------
// Scratch (device globals; allocation-free, graph-capture safe)
// ---------------------------------------------------------------------------
__device__ __align__(16) __half g_msa_h[MROWS * DMODEL];        // fp16 msa [32768][256]
__device__ __align__(16) __half g_wqkv_t[3 * DMODEL * DMODEL];  // [768][256]  (N-major, K contiguous)
__device__ __align__(16) __half g_wout_t[DMODEL * DMODEL];      // [256][256]
__device__ __align__(16) __half g_qkv_h[MROWS * 3 * DMODEL];    // [32768][768]
__device__ __align__(16) __half g_att_h[MROWS * DMODEL];        // [32768][256]
__device__ float g_bias[HEADS * LSEQ * LSEQ];                   // [h][q][k]

// ---------------------------------------------------------------------------
// helpers
// ---------------------------------------------------------------------------
__device__ __forceinline__ uint32_t smem_u32(const void* p) {
    uint32_t a;
    asm("{ .reg .u64 t; cvta.to.shared.u64 t, %1; cvt.u32.u64 %0, t; }" : "=r"(a) : "l"(p));
    return a;
}

#define LDMX4(r0, r1, r2, r3, addr)                                           \
    asm volatile("ldmatrix.sync.aligned.m8n8.x4.shared.b16 {%0,%1,%2,%3}, [%4];" \
                 : "=r"(r0), "=r"(r1), "=r"(r2), "=r"(r3) : "r"(addr))

#define LDMX4T(r0, r1, r2, r3, addr)                                          \
    asm volatile("ldmatrix.sync.aligned.m8n8.x4.trans.shared.b16 {%0,%1,%2,%3}, [%4];" \
                 : "=r"(r0), "=r"(r1), "=r"(r2), "=r"(r3) : "r"(addr))

__device__ __forceinline__ void mma16816(float* c, const uint32_t* a, const uint32_t* b) {
    asm volatile("mma.sync.aligned.m16n8k16.row.col.f32.f16.f16.f32 "
                 "{%0,%1,%2,%3}, {%4,%5,%6,%7}, {%8,%9}, {%0,%1,%2,%3};"
                 : "+f"(c[0]), "+f"(c[1]), "+f"(c[2]), "+f"(c[3])
                 : "r"(a[0]), "r"(a[1]), "r"(a[2]), "r"(a[3]), "r"(b[0]), "r"(b[1]));
}

#define CP_ASYNC16(dst, src) \
    asm volatile("cp.async.cg.shared.global [%0], [%1], 16;" :: "r"(dst), "l"(src))
#define CP_COMMIT() asm volatile("cp.async.commit_group;" ::: "memory")
#define CP_WAIT(n)  asm volatile("cp.async.wait_group %0;" :: "n"(n) : "memory")

// ---------------------------------------------------------------------------
// HMMA GEMM, cp.async 3-stage pipeline: C[M,N] = A[M,256] @ Bt[N,256]^T.
// Block tile 64(M)x128(N); K chunked by 64 (4 chunks, 3 stages of 24KB).
// 8 warps each 16(M)x64(N). ~2 CTAs/SM for latency hiding.
// ---------------------------------------------------------------------------
template <bool FINAL>
__global__ void __launch_bounds__(256) gemm_hmma(
    const __half* __restrict__ A, const __half* __restrict__ Bt,
    __half* __restrict__ Ch, float* __restrict__ Cf,
    const float* __restrict__ bias, int ldc)
{
    extern __shared__ __align__(16) char sm[];  // 3 stages x (A 8KB + B 16KB)

    const int tid = threadIdx.x;
    const int wid = tid >> 5, lane = tid & 31;
    const int m0 = blockIdx.y << 6;
    const int n0 = blockIdx.x << 7;
    const uint32_t smbase = smem_u32(sm);

    auto load_stage = [&](int s, int kc) {
        const uint32_t base = smbase + s * 24576;
#pragma unroll
        for (int i = 0; i < 6; i++) {
            const int idx = tid + i * 256;   // 0..1535
            if (idx < 512) {
                const int r = idx >> 3, c = idx & 7;
                const __half* src = A + (size_t)(m0 + r) * 256 + kc * 64 + c * 8;
                CP_ASYNC16(base + r * 128 + ((c ^ (r & 7)) << 4), src);
            } else {
                const int j = idx - 512;
                const int r = j >> 3, c = j & 7;
                const __half* src = Bt + (size_t)(n0 + r) * 256 + kc * 64 + c * 8;
                CP_ASYNC16(base + 8192 + r * 128 + ((c ^ (r & 7)) << 4), src);
            }
        }
        CP_COMMIT();
    };

    const int wm = (wid >> 1) << 4;    // 0,16,32,48
    const int wn = (wid & 1) << 6;     // 0,64
    const int a_row = (lane & 7) + ((lane >> 3) & 1) * 8;
    const int a_cadd = lane >> 4;
    const int b_row = (lane & 7) + ((lane >> 4) & 1) * 8;
    const int b_cadd = (lane >> 3) & 1;

    const int a_r = wm + a_row;
    int b_r[4];
#pragma unroll
    for (int j = 0; j < 4; j++) b_r[j] = wn + 16 * j + b_row;

    float acc[8][4];
#pragma unroll
    for (int j = 0; j < 8; j++)
#pragma unroll
        for (int t = 0; t < 4; t++) acc[j][t] = 0.f;

    auto compute_chunk = [&](int s) {
        const uint32_t baseA = smbase + s * 24576;
        const uint32_t baseB = baseA + 8192;
#pragma unroll
        for (int kk = 0; kk < 4; kk++) {
            const int k8 = kk * 2;
            uint32_t a[4];
            {
                const uint32_t addr = baseA + a_r * 128 +
                                      (((k8 + a_cadd) ^ (a_r & 7)) << 4);
                LDMX4(a[0], a[1], a[2], a[3], addr);
            }
            uint32_t b[8][2];
#pragma unroll
            for (int j = 0; j < 4; j++) {
                const uint32_t addr = baseB + b_r[j] * 128 +
                                      (((k8 + b_cadd) ^ (b_r[j] & 7)) << 4);
                LDMX4(b[2 * j][0], b[2 * j][1], b[2 * j + 1][0], b[2 * j + 1][1], addr);
            }
#pragma unroll
            for (int j = 0; j < 8; j++)
                mma16816(acc[j], a, b[j]);
        }
    };

    load_stage(0, 0);
    load_stage(1, 1);
    load_stage(2, 2);

    CP_WAIT(2); __syncthreads();
    compute_chunk(0);
    __syncthreads();
    load_stage(0, 3);

    CP_WAIT(2); __syncthreads();
    compute_chunk(1);

    CP_WAIT(1); __syncthreads();
    compute_chunk(2);

    CP_WAIT(0); __syncthreads();
    compute_chunk(0);

    const int tr = lane >> 2;
    const int tc = (lane & 3) * 2;
    const int row = m0 + wm + tr;
#pragma unroll
    for (int j = 0; j < 8; j++) {
        const int col = n0 + wn + 8 * j + tc;
        if (FINAL) {
            const float b0 = __ldg(&bias[col]), b1 = __ldg(&bias[col + 1]);
            float2 v0 = make_float2(acc[j][0] + b0, acc[j][1] + b1);
            float2 v1 = make_float2(acc[j][2] + b0, acc[j][3] + b1);
            *(float2*)(Cf + (size_t)row * ldc + col) = v0;
            *(float2*)(Cf + (size_t)(row + 8) * ldc + col) = v1;
        } else {
            __half2 h0 = __floats2half2_rn(acc[j][0], acc[j][1]);
            __half2 h1 = __floats2half2_rn(acc[j][2], acc[j][3]);
            *(__half2*)(Ch + (size_t)row * ldc + col) = h0;
            *(__half2*)(Ch + (size_t)(row + 8) * ldc + col) = h1;
        }
    }
}

// ---------------------------------------------------------------------------
// fp32 -> fp16 bulk convert
// ---------------------------------------------------------------------------
__global__ void __launch_bounds__(512) cvt_msa_kernel(const float4* __restrict__ in,
                                                      __half2* __restrict__ out, int n4)
{
    for (int i = blockIdx.x * 512 + threadIdx.x; i < n4; i += gridDim.x * 512) {
        float4 v = in[i];
        out[2 * i]     = __floats2half2_rn(v.x, v.y);
        out[2 * i + 1] = __floats2half2_rn(v.z, v.w);
    }
}

// transpose + convert: out[n*256 + k] = in[k*N + n]  (K fixed at 256)
__global__ void __launch_bounds__(256) cvt_wT_kernel(const float* __restrict__ in,
                                                     __half* __restrict__ out, int N)
{
    int idx = blockIdx.x * 256 + threadIdx.x;
    if (idx < N * 256) {
        int n = idx >> 8, k = idx & 255;
        out[idx] = __float2half(in[k * N + n]);
    }
}

// ---------------------------------------------------------------------------
// pair_bias: bias[h][q][k] = sum_p pair[q][k][p] * w_pb[p][h] + b_pb[h]
// ---------------------------------------------------------------------------
__global__ void __launch_bounds__(256) pair_bias_kernel(
    const float* __restrict__ pair, const float* __restrict__ w_pb,
    const float* __restrict__ b_pb, float* __restrict__ bias_out)
{
    __shared__ float w[PDIM * HEADS];
    __shared__ float bb[HEADS];
    const int tid = threadIdx.x;
    for (int i = tid; i < PDIM * HEADS; i += 256) w[i] = w_pb[i];
    if (tid < HEADS) bb[tid] = b_pb[tid];
    __syncthreads();

    const int warp = (blockIdx.x << 3) + (tid >> 5);
    const int lane = tid & 31;
    const int q = warp >> 8;
    const int k = warp & 255;

    float4 p = *(const float4*)(pair + ((size_t)(q << 8) + k) * PDIM + (lane << 2));
    const int p0 = lane << 2;

    float res[HEADS];
#pragma unroll
    for (int h = 0; h < HEADS; h++) {
        float s = p.x * w[(p0 + 0) * HEADS + h]
                + p.y * w[(p0 + 1) * HEADS + h]
                + p.z * w[(p0 + 2) * HEADS + h]
                + p.w * w[(p0 + 3) * HEADS + h];
#pragma unroll
        for (int off = 16; off; off >>= 1)
            s += __shfl_xor_sync(0xFFFFFFFFu, s, off);
        res[h] = s + bb[h];
    }
    if (lane == 0) {
#pragma unroll
        for (int h = 0; h < HEADS; h++)
            bias_out[((size_t)(h << 8) + q) * LSEQ + k] = res[h];
    }
}

// ---------------------------------------------------------------------------
// Attention v4: HMMA flash-attention. One CTA per (n,h,64-q-chunk): 4096 CTAs,
// 128 threads (4 warps x 16 q-rows). K/V full 256 rows in smem (L2-resident
// gmem source). Online softmax with masked max; P repacked to fp16 A-frags.
// ---------------------------------------------------------------------------
__global__ void __launch_bounds__(128) attn_kernel(
    const int* __restrict__ mask, const __half* __restrict__ qkv,
    const float* __restrict__ bias, __half* __restrict__ outh)
{
    extern __shared__ __align__(16) __half smh[];
    __half* Qs = smh;                 // 64 rows x 40 halfs (80B pitch)
    __half* Ks = smh + 2560;          // 256 x 40
    __half* Vs = smh + 12800;         // 256 x 40
    float* maskf = (float*)(smh + 23040);  // 256 floats

    const int bx = blockIdx.x;
    const int n = bx >> 5;
    const int h = (bx >> 2) & 7;
    const int qb = (bx & 3) << 6;
    const int tid = threadIdx.x;
    const int wid = tid >> 5, lane = tid & 31;

    const __half* basep = qkv + (size_t)(n * LSEQ) * 768 + h * DHEAD;
    // K/V: 256 rows x 4 units
    for (int u = tid; u < 1024; u += 128) {
        const int l = u >> 2, c = u & 3;
        const __half* r = basep + (size_t)l * 768 + c * 8;
        *(uint4*)&Ks[l * 40 + c * 8] = *(const uint4*)(r + 256);
        *(uint4*)&Vs[l * 40 + c * 8] = *(const uint4*)(r + 512);
    }
    // Q: 64 rows x 4 units
    for (int u = tid; u < 256; u += 128) {
        const int l = u >> 2, c = u & 3;
        *(uint4*)&Qs[l * 40 + c * 8] = *(const uint4*)(basep + (size_t)(qb + l) * 768 + c * 8);
    }
    maskf[tid] = mask[n * LSEQ + tid] ? 1.0f : 0.0f;
    maskf[tid + 128] = mask[n * LSEQ + tid + 128] ? 1.0f : 0.0f;
    __syncthreads();

    const uint32_t Qa = smem_u32(Qs), Ka = smem_u32(Ks), Va = smem_u32(Vs);
    const int wq0 = wid * 16;
    const int a_row = (lane & 7) + ((lane >> 3) & 1) * 8;
    const int a_c = lane >> 4;
    const int b_row = (lane & 7) + ((lane >> 4) & 1) * 8;
    const int b_c = (lane >> 3) & 1;
    const int tr = lane >> 2, tc = (lane & 3) * 2;

    // Q fragments (persistent)
    uint32_t aq[2][4];
#pragma unroll
    for (int kt = 0; kt < 2; kt++) {
        const uint32_t addr = Qa + (wq0 + a_row) * 80 + (kt * 2 + a_c) * 16;
        LDMX4(aq[kt][0], aq[kt][1], aq[kt][2], aq[kt][3], addr);
    }

    float o[4][4];
#pragma unroll
    for (int nt = 0; nt < 4; nt++)
#pragma unroll
        for (int t = 0; t < 4; t++) o[nt][t] = 0.f;
    float rsum[2] = {0.f, 0.f};
    float rmax[2] = {-1e30f, -1e30f};

    const float scale = 0.17677669529663687f;  // 1/sqrt(32)
    const float* bias_h = bias + (size_t)h * LSEQ * LSEQ;  // [q][k]

    for (int j = 0; j < 4; j++) {
        const int kb = j * 64;

        // K fragments
        uint32_t bk[4][2][4];
#pragma unroll
        for (int kg = 0; kg < 4; kg++)
#pragma unroll
            for (int kt = 0; kt < 2; kt++) {
                const uint32_t addr = Ka + (kb + kg * 16 + b_row) * 80 + (kt * 2 + b_c) * 16;
                LDMX4(bk[kg][kt][0], bk[kg][kt][1], bk[kg][kt][2], bk[kg][kt][3], addr);
            }

        // S = Q K^T
        float s[8][4];
#pragma unroll
        for (int nn = 0; nn < 8; nn++) {
#pragma unroll
            for (int t = 0; t < 4; t++) s[nn][t] = 0.f;
#pragma unroll
            for (int kt = 0; kt < 2; kt++)
                mma16816(s[nn], aq[kt], &bk[nn >> 1][kt][(nn & 1) * 2]);
        }

        // scale + bias, masked running max
        float cmax[2] = {-1e30f, -1e30f};
        {
            const float* br0 = bias_h + (size_t)(qb + wq0 + tr) * 256 + kb;
            const float* br1 = br0 + 8 * 256;
#pragma unroll
            for (int nn = 0; nn < 8; nn++) {
                const int kc = nn * 8 + tc;
                float2 mf = *(float2*)&maskf[kb + kc];
                float2 b0 = *(const float2*)(br0 + kc);
                float2 b1 = *(const float2*)(br1 + kc);
                float v0 = fmaf(s[nn][0], scale, b0.x);
                float v1 = fmaf(s[nn][1], scale, b0.y);
                float v2 = fmaf(s[nn][2], scale, b1.x);
                float v3 = fmaf(s[nn][3], scale, b1.y);
                s[nn][0] = v0; s[nn][1] = v1; s[nn][2] = v2; s[nn][3] = v3;
                cmax[0] = fmaxf(cmax[0], mf.x > 0.f ? v0 : -1e30f);
                cmax[0] = fmaxf(cmax[0], mf.y > 0.f ? v1 : -1e30f);
                cmax[1] = fmaxf(cmax[1], mf.x > 0.f ? v2 : -1e30f);
                cmax[1] = fmaxf(cmax[1], mf.y > 0.f ? v3 : -1e30f);
            }
        }

        // quad-reduce max, rescale running state
        float sf[2];
#pragma unroll
        for (int r = 0; r < 2; r++) {
            float v = cmax[r];
            v = fmaxf(v, __shfl_xor_sync(0xFFFFFFFFu, v, 1));
            v = fmaxf(v, __shfl_xor_sync(0xFFFFFFFFu, v, 2));
            const float mnew = fmaxf(rmax[r], v);
            sf[r] = __expf(rmax[r] - mnew);
            rmax[r] = mnew;
            rsum[r] *= sf[r];
        }
#pragma unroll
        for (int nt = 0; nt < 4; nt++) {
            o[nt][0] *= sf[0]; o[nt][1] *= sf[0];
            o[nt][2] *= sf[1]; o[nt][3] *= sf[1];
        }

        // exp + mask, pack P to fp16 A-fragments
        uint32_t ap[4][4];
#pragma unroll
        for (int nn = 0; nn < 8; nn++) {
            const int kc = nn * 8 + tc;
            float2 mf = *(float2*)&maskf[kb + kc];
            float p0 = __expf(fminf(s[nn][0] - rmax[0], 0.f)) * mf.x;
            float p1 = __expf(fminf(s[nn][1] - rmax[0], 0.f)) * mf.y;
            float p2 = __expf(fminf(s[nn][2] - rmax[1], 0.f)) * mf.x;
            float p3 = __expf(fminf(s[nn][3] - rmax[1], 0.f)) * mf.y;
            rsum[0] += p0 + p1;
            rsum[1] += p2 + p3;
            __half2 h01 = __floats2half2_rn(p0, p1);
            __half2 h23 = __floats2half2_rn(p2, p3);
            const int kt = nn >> 1, half_ = (nn & 1) * 2;
            ap[kt][half_ + 0] = *(uint32_t*)&h01;
            ap[kt][half_ + 1] = *(uint32_t*)&h23;
        }

        // V fragments (trans)
        uint32_t bv[4][4][2];
#pragma unroll
        for (int kg = 0; kg < 4; kg++)
#pragma unroll
            for (int dh = 0; dh < 2; dh++) {
                uint32_t r0, r1, r2, r3;
                const uint32_t addr = Va + (kb + kg * 16 + a_row) * 80 + (dh * 2 + a_c) * 16;
                LDMX4T(r0, r1, r2, r3, addr);
                bv[kg][dh * 2][0] = r0;     bv[kg][dh * 2][1] = r1;
                bv[kg][dh * 2 + 1][0] = r2; bv[kg][dh * 2 + 1][1] = r3;
            }

        // O += P V
#pragma unroll
        for (int nt = 0; nt < 4; nt++)
#pragma unroll
            for (int kt = 0; kt < 4; kt++)
                mma16816(o[nt], ap[kt], bv[kt][nt]);
    }

    // final row-sum reduce and normalize
    float inv[2];
#pragma unroll
    for (int r = 0; r < 2; r++) {
        float v = rsum[r];
        v += __shfl_xor_sync(0xFFFFFFFFu, v, 1);
        v += __shfl_xor_sync(0xFFFFFFFFu, v, 2);
        inv[r] = (v > 0.f) ? (1.0f / v) : 0.f;
    }

    const size_t q0 = (size_t)(n * LSEQ + qb + wq0 + tr);
    const int dcol = h * DHEAD + tc;
#pragma unroll
    for (int nt = 0; nt < 4; nt++) {
        __half2 h0 = __floats2half2_rn(o[nt][0] * inv[0], o[nt][1] * inv[0]);
        __half2 h1 = __floats2half2_rn(o[nt][2] * inv[1], o[nt][3] * inv[1]);
        *(__half2*)(outh + q0 * DMODEL + dcol + nt * 8) = h0;
        *(__half2*)(outh + (q0 + 8) * DMODEL + dcol + nt * 8) = h1;
    }
}

// ---------------------------------------------------------------------------
// Launch (fork-join stream overlap, capture-legal event pattern)
// ---------------------------------------------------------------------------
extern "C" void kernel_launch(void* const* d_in, const int* in_sizes, int n_in,
                              void* d_out, int out_size)
{
    const float* msa   = (const float*)d_in[0];
    const float* pair  = (const float*)d_in[1];
    const int*   mask  = (const int*)d_in[2];
    const float* w_qkv = (const float*)d_in[3];
    const float* w_pb  = (const float*)d_in[4];
    const float* b_pb  = (const float*)d_in[5];
    const float* w_out = (const float*)d_in[6];
    const float* b_out = (const float*)d_in[7];
    float* out = (float*)d_out;

    __half *msa_h, *wqkv_t, *wout_t, *qkv_h, *att_h;
    float* bias_ptr;
    cudaGetSymbolAddress((void**)&msa_h,   g_msa_h);
    cudaGetSymbolAddress((void**)&wqkv_t,  g_wqkv_t);
    cudaGetSymbolAddress((void**)&wout_t,  g_wout_t);
    cudaGetSymbolAddress((void**)&qkv_h,   g_qkv_h);
    cudaGetSymbolAddress((void**)&att_h,   g_att_h);
    cudaGetSymbolAddress((void**)&bias_ptr, g_bias);

    static cudaStream_t s2 = nullptr;
    static cudaEvent_t ev_fork = nullptr, ev_join = nullptr;
    if (s2 == nullptr) {
        cudaStreamCreateWithFlags(&s2, cudaStreamNonBlocking);
        cudaEventCreateWithFlags(&ev_fork, cudaEventDisableTiming);
        cudaEventCreateWithFlags(&ev_join, cudaEventDisableTiming);
    }

    const int gemm_smem = 3 * 24576;  // 72KB
    cudaFuncSetAttribute(gemm_hmma<false>, cudaFuncAttributeMaxDynamicSharedMemorySize, gemm_smem);
    cudaFuncSetAttribute(gemm_hmma<true>,  cudaFuncAttributeMaxDynamicSharedMemorySize, gemm_smem);
    const int attn_smem = 23040 * 2 + 1024;  // 47104
    cudaFuncSetAttribute(attn_kernel, cudaFuncAttributeMaxDynamicSharedMemorySize, attn_smem);

    // fork: side stream runs pair_bias + w_out transpose
    cudaEventRecord(ev_fork, 0);
    cudaStreamWaitEvent(s2, ev_fork, 0);
    pair_bias_kernel<<<8192, 256, 0, s2>>>(pair, w_pb, b_pb, bias_ptr);
    cvt_wT_kernel<<<(DMODEL * DMODEL + 255) / 256, 256, 0, s2>>>(w_out, wout_t, DMODEL);
    cudaEventRecord(ev_join, s2);

    // main stream: converts + QKV GEMM
    cvt_msa_kernel<<<2048, 512>>>((const float4*)msa, (__half2*)msa_h, MROWS * DMODEL / 4);
    cvt_wT_kernel<<<(3 * DMODEL * DMODEL + 255) / 256, 256>>>(w_qkv, wqkv_t, 3 * DMODEL);
    gemm_hmma<false><<<dim3(6, 512), 256, gemm_smem>>>(msa_h, wqkv_t, qkv_h, nullptr, nullptr, 768);

    // join: attention needs pair_bias; out-proj needs wout_t
    cudaStreamWaitEvent(0, ev_join, 0);
    attn_kernel<<<NSEQ * HEADS * 4, 128, attn_smem>>>(mask, qkv_h, bias_ptr, att_h);
    gemm_hmma<true><<<dim3(2, 512), 256, gemm_smem>>>(att_h, wout_t, nullptr, out, b_out, 256);
}